// round 14
// baseline (speedup 1.0000x reference)
#include <cuda_runtime.h>

#define BATCHN 8192
#define SEQ 100
#define EMBED 50
#define HID 20
#define NLABEL 15
#define G3 60
#define VOCAB 50000

typedef unsigned long long ull;

// scratch: PW1[v] = emb[v] @ W1 + b1_input, pair-col-packed (col j, col j+32)
__device__ ull d_PW1p[(size_t)VOCAB * 32];

__device__ __forceinline__ ull pack2(float x) {
    ull d; asm("mov.b64 %0, {%1, %1};" : "=l"(d) : "f"(x)); return d;
}
__device__ __forceinline__ ull packab(float a, float b) {
    ull d; asm("mov.b64 %0, {%1, %2};" : "=l"(d) : "f"(a), "f"(b)); return d;
}
__device__ __forceinline__ void unpk(ull v, float &a, float &b) {
    asm("mov.b64 {%0, %1}, %2;" : "=f"(a), "=f"(b) : "l"(v));
}
__device__ __forceinline__ ull ffma2(ull a, ull b, ull c) {
    ull d; asm("fma.rn.f32x2 %0, %1, %2, %3;" : "=l"(d) : "l"(a), "l"(b), "l"(c)); return d;
}
__device__ __forceinline__ ull add2(ull a, ull b) {
    ull d; asm("add.rn.f32x2 %0, %1, %2;" : "=l"(d) : "l"(a), "l"(b)); return d;
}
// HW tanh (MUFU.TANH): 1 MUFU op, ~16 cyc. abs err ~1e-4 for small |x|.
__device__ __forceinline__ float tanhfast(float x) {
    float y; asm("tanh.approx.f32 %0, %1;" : "=f"(y) : "f"(x)); return y;
}
__device__ __forceinline__ float sigm(float x) {
    return fmaf(0.5f, tanhfast(0.5f * x), 0.5f);
}
__device__ __forceinline__ float tanh_(float x) {
    return tanhfast(x);
}

// ============================================================================
// proj: PW1[v] = emb[v]@W1 + bi1 (block-tiled, coalesced)
// ============================================================================
__global__ void __launch_bounds__(128) proj1_kernel(
    const float* __restrict__ emb, const float* __restrict__ W1,
    const float* __restrict__ b1)
{
    __shared__ __align__(16) ull sx[32 * EMBED];
    const int tid = threadIdx.x;
    const int w = tid >> 5, j = tid & 31;

    ull w1r[EMBED];
    #pragma unroll
    for (int k = 0; k < EMBED; k++) {
        float lo = W1[k * G3 + j];
        float hi = (j + 32 < G3) ? W1[k * G3 + j + 32] : 0.f;
        w1r[k] = packab(lo, hi);
    }
    const ull bias = packab(b1[j], (j + 32 < G3) ? b1[j + 32] : 0.f);

    const int ntiles = (VOCAB + 31) / 32;
    for (int tile = blockIdx.x; tile < ntiles; tile += gridDim.x) {
        const int row0 = tile * 32;
        const int nrow = (VOCAB - row0 < 32) ? (VOCAB - row0) : 32;
        for (int i = tid; i < nrow * EMBED; i += 128)
            sx[i] = pack2(emb[(size_t)row0 * EMBED + i]);
        __syncthreads();
        #pragma unroll
        for (int rr = 0; rr < 8; rr++) {
            int lr = w * 8 + rr;
            if (row0 + lr < VOCAB) {
                ull acc = bias;
                #pragma unroll
                for (int k = 0; k < EMBED; k += 2) {
                    ulonglong2 xv = *(const ulonglong2*)&sx[lr * EMBED + k];
                    acc = ffma2(xv.x, w1r[k], acc);
                    acc = ffma2(xv.y, w1r[k + 1], acc);
                }
                d_PW1p[(size_t)(row0 + lr) * 32 + j] = acc;
            }
        }
        __syncthreads();
    }
}

// ============================================================================
// Gate evaluation for one (q, i) unit: reads batch-paired sums, writes h
// batch-paired. tanh.approx-based gates (3 MUFU / unit).
// ============================================================================
__device__ __forceinline__ void gate_unit(
    const ull* __restrict__ ssg, const ull* __restrict__ smhg,
    ull* __restrict__ shg, int q, int i, float &hpa, float &hpb)
{
    float z0, z1, r0, r1, x0, x1, m0, m1;
    unpk(ssg[q * 64 + i],      z0, z1);
    unpk(ssg[q * 64 + i + 20], r0, r1);
    unpk(ssg[q * 64 + i + 40], x0, x1);
    unpk(smhg[q * 24 + i],     m0, m1);
    float za = sigm(z0), zb = sigm(z1);
    float ra = sigm(r0), rb = sigm(r1);
    float ha = tanh_(fmaf(ra, m0, x0));
    float hb = tanh_(fmaf(rb, m1, x1));
    float n0 = fmaf(za, hpa - ha, ha);
    float n1 = fmaf(zb, hpb - hb, hb);
    hpa = n0; hpb = n1;
    shg[q * HID + i] = packab(n0, n1);
}

// ============================================================================
// Fused 2-layer GRU. E=8/warp: 16 col-lanes x 2 batch-groups, batch-paired h,
// in-register weight dup, interleaved-k weight layout (LDS.128).
// One warp per block, 1024 blocks, syncwarp-only.
// ============================================================================
__global__ void __launch_bounds__(32) wordrnn_kernel(
    const int* __restrict__ xg,
    const float* __restrict__ U1f, const float* __restrict__ b1,
    const float* __restrict__ W2f, const float* __restrict__ b2,
    const float* __restrict__ U2f,
    const float* __restrict__ Wd, const float* __restrict__ bd,
    float* __restrict__ out)
{
    // [kp][c] = { pack(M[2kp][c], M[2kp][c+32]), pack(M[2kp+1][c], M[2kp+1][c+32]) }
    __shared__ __align__(16) ulonglong2 sU1[HID / 2][32];
    __shared__ __align__(16) ulonglong2 sW2[HID / 2][32];
    __shared__ __align__(16) ulonglong2 sU2[HID / 2][32];
    __shared__ __align__(16) ull sh1[2][2][HID];   // [group][pair][k] = (h_e0, h_e1)
    __shared__ __align__(16) ull sh2[2][2][HID];
    __shared__ ull ss[2][2][64];                   // batch-paired gate sums
    __shared__ ull smh[2][2][24];                  // h-gate recurrent part
    __shared__ int sxi[8][SEQ];

    const int l = threadIdx.x;
    const int g = l >> 4, lc = l & 15;
    const int b0 = blockIdx.x * 8;

    // stage weights: interleaved-k pair-packed layout
    for (int i = l; i < (HID / 2) * 32; i += 32) {
        int kp = i >> 5, c = i & 31;
        bool ok = (c + 32 < G3);
        int ch = ok ? c + 32 : 0;
        int k0 = 2 * kp, k1 = 2 * kp + 1;
        sU1[kp][c] = make_ulonglong2(
            packab(U1f[k0 * G3 + c], ok ? U1f[k0 * G3 + ch] : 0.f),
            packab(U1f[k1 * G3 + c], ok ? U1f[k1 * G3 + ch] : 0.f));
        sW2[kp][c] = make_ulonglong2(
            packab(W2f[k0 * G3 + c], ok ? W2f[k0 * G3 + ch] : 0.f),
            packab(W2f[k1 * G3 + c], ok ? W2f[k1 * G3 + ch] : 0.f));
        sU2[kp][c] = make_ulonglong2(
            packab(U2f[k0 * G3 + c], ok ? U2f[k0 * G3 + ch] : 0.f),
            packab(U2f[k1 * G3 + c], ok ? U2f[k1 * G3 + ch] : 0.f));
    }
    // stage indices: 8 rows x 100
    for (int i = l; i < 8 * 25; i += 32) {
        int r = i / 25, c = i % 25;
        *(int4*)&sxi[r][c * 4] = *(const int4*)(xg + (size_t)(b0 + r) * SEQ + c * 4);
    }
    for (int i = l; i < 2 * 2 * HID; i += 32) {
        ((ull*)sh1)[i] = 0ull;
        ((ull*)sh2)[i] = 0ull;
    }
    __syncwarp();

    // biases for this lane's col pairs p0=lc, p1=lc+16
    const int p0 = lc, p1 = lc + 16;
    const bool h1ok = (lc + 48 < G3);     // validity of col p1+32
    const ull br1L0 = pack2(b1[G3 + p0]), br1H0 = pack2(b1[G3 + p0 + 32]);
    const ull br1L1 = pack2(b1[G3 + p1]), br1H1 = pack2(h1ok ? b1[G3 + p1 + 32] : 0.f);
    const ull bi2L0 = pack2(b2[p0]),      bi2H0 = pack2(b2[p0 + 32]);
    const ull bi2L1 = pack2(b2[p1]),      bi2H1 = pack2(h1ok ? b2[p1 + 32] : 0.f);
    const ull br2L0 = pack2(b2[G3 + p0]), br2H0 = pack2(b2[G3 + p0 + 32]);
    const ull br2L1 = pack2(b2[G3 + p1]), br2H1 = pack2(h1ok ? b2[G3 + p1 + 32] : 0.f);

    // hprev for the 3 gate rounds (round -> fixed (q,i) per lane), 2 elems each
    float hp1[3][2] = {{0.f,0.f},{0.f,0.f},{0.f,0.f}};
    float hp2[3][2] = {{0.f,0.f},{0.f,0.f},{0.f,0.f}};
    const int q1r = (lc >= 4) ? 1 : 0;
    const int i1r = (lc < 4) ? 16 + lc : lc - 4;

    const ull* __restrict__ pw0 = d_PW1p + p0;
    const ull* __restrict__ pw1 = d_PW1p + p1;

    // t=0 input projection gather + 2x2 transpose into batch-pair packing
    ull axL[2][2], axH[2][2];
    #pragma unroll
    for (int q = 0; q < 2; q++) {
        int e0 = 4 * g + 2 * q;
        size_t i0 = (size_t)sxi[e0][0] * 32, i1 = (size_t)sxi[e0 + 1][0] * 32;
        ull ga = __ldg(pw0 + i0), gb = __ldg(pw0 + i1);
        ull gc = __ldg(pw1 + i0), gd = __ldg(pw1 + i1);
        float a0, a1, bb0, bb1, c0, c1, d0, d1;
        unpk(ga, a0, a1); unpk(gb, bb0, bb1);
        unpk(gc, c0, c1); unpk(gd, d0, d1);
        axL[0][q] = packab(a0, bb0); axH[0][q] = packab(a1, bb1);
        axL[1][q] = packab(c0, d0);  axH[1][q] = packab(c1, d1);
    }

    for (int t = 0; t < SEQ; t++) {
        // ================= layer 1: ah = h1 @ U1 + br1 =================
        ull aL[2][2], aH[2][2];
        aL[0][0] = br1L0; aL[0][1] = br1L0; aH[0][0] = br1H0; aH[0][1] = br1H0;
        aL[1][0] = br1L1; aL[1][1] = br1L1; aH[1][0] = br1H1; aH[1][1] = br1H1;
        #pragma unroll
        for (int kp = 0; kp < HID / 2; kp++) {
            const int k = kp * 2;
            ulonglong2 wv0 = sU1[kp][lc], wv1 = sU1[kp][lc + 16];
            float t0, t1;
            unpk(wv0.x, t0, t1); ull wA0l = pack2(t0), wA0h = pack2(t1);
            unpk(wv1.x, t0, t1); ull wA1l = pack2(t0), wA1h = pack2(t1);
            unpk(wv0.y, t0, t1); ull wB0l = pack2(t0), wB0h = pack2(t1);
            unpk(wv1.y, t0, t1); ull wB1l = pack2(t0), wB1h = pack2(t1);
            ulonglong2 hv0 = *(const ulonglong2*)&sh1[g][0][k];
            ulonglong2 hv1 = *(const ulonglong2*)&sh1[g][1][k];
            aL[0][0] = ffma2(hv0.x, wA0l, aL[0][0]); aH[0][0] = ffma2(hv0.x, wA0h, aH[0][0]);
            aL[1][0] = ffma2(hv0.x, wA1l, aL[1][0]); aH[1][0] = ffma2(hv0.x, wA1h, aH[1][0]);
            aL[0][0] = ffma2(hv0.y, wB0l, aL[0][0]); aH[0][0] = ffma2(hv0.y, wB0h, aH[0][0]);
            aL[1][0] = ffma2(hv0.y, wB1l, aL[1][0]); aH[1][0] = ffma2(hv0.y, wB1h, aH[1][0]);
            aL[0][1] = ffma2(hv1.x, wA0l, aL[0][1]); aH[0][1] = ffma2(hv1.x, wA0h, aH[0][1]);
            aL[1][1] = ffma2(hv1.x, wA1l, aL[1][1]); aH[1][1] = ffma2(hv1.x, wA1h, aH[1][1]);
            aL[0][1] = ffma2(hv1.y, wB0l, aL[0][1]); aH[0][1] = ffma2(hv1.y, wB0h, aH[0][1]);
            aL[1][1] = ffma2(hv1.y, wB1l, aL[1][1]); aH[1][1] = ffma2(hv1.y, wB1h, aH[1][1]);
        }
        #pragma unroll
        for (int q = 0; q < 2; q++) {
            ss[g][q][lc]      = add2(axL[0][q], aL[0][q]);
            ss[g][q][lc + 16] = add2(axL[1][q], aL[1][q]);
            if (lc < 8) ss[g][q][lc + 32] = add2(axH[0][q], aH[0][q]);
            else { ss[g][q][lc + 32] = axH[0][q]; smh[g][q][lc - 8] = aH[0][q]; }
            ss[g][q][lc + 48] = axH[1][q];
            smh[g][q][lc + 8] = aH[1][q];
        }
        __syncwarp();
        {
            const ull* ssg  = &ss[g][0][0];
            const ull* smhg = &smh[g][0][0];
            ull* shg = &sh1[g][0][0];
            gate_unit(ssg, smhg, shg, 0, lc, hp1[0][0], hp1[0][1]);
            gate_unit(ssg, smhg, shg, q1r, i1r, hp1[1][0], hp1[1][1]);
            if (lc < 8) gate_unit(ssg, smhg, shg, 1, 12 + lc, hp1[2][0], hp1[2][1]);
        }
        __syncwarp();

        // prefetch next step's input projection (covered by layer-2 work)
        if (t + 1 < SEQ) {
            #pragma unroll
            for (int q = 0; q < 2; q++) {
                int e0 = 4 * g + 2 * q;
                size_t i0 = (size_t)sxi[e0][t + 1] * 32, i1 = (size_t)sxi[e0 + 1][t + 1] * 32;
                ull ga = __ldg(pw0 + i0), gb = __ldg(pw0 + i1);
                ull gc = __ldg(pw1 + i0), gd = __ldg(pw1 + i1);
                float a0, a1, bb0, bb1, c0, c1, d0, d1;
                unpk(ga, a0, a1); unpk(gb, bb0, bb1);
                unpk(gc, c0, c1); unpk(gd, d0, d1);
                axL[0][q] = packab(a0, bb0); axH[0][q] = packab(a1, bb1);
                axL[1][q] = packab(c0, d0);  axH[1][q] = packab(c1, d1);
            }
        }

        // ========== layer 2: m = h1@W2+bi2 ; c = h2@U2+br2 ==========
        ull mL[2][2], mH[2][2], cL[2][2], cH[2][2];
        mL[0][0] = bi2L0; mL[0][1] = bi2L0; mH[0][0] = bi2H0; mH[0][1] = bi2H0;
        mL[1][0] = bi2L1; mL[1][1] = bi2L1; mH[1][0] = bi2H1; mH[1][1] = bi2H1;
        cL[0][0] = br2L0; cL[0][1] = br2L0; cH[0][0] = br2H0; cH[0][1] = br2H0;
        cL[1][0] = br2L1; cL[1][1] = br2L1; cH[1][0] = br2H1; cH[1][1] = br2H1;
        #pragma unroll
        for (int kp = 0; kp < HID / 2; kp++) {
            const int k = kp * 2;
            ulonglong2 wv0 = sW2[kp][lc], wv1 = sW2[kp][lc + 16];
            ulonglong2 uv0 = sU2[kp][lc], uv1 = sU2[kp][lc + 16];
            float t0, t1;
            unpk(wv0.x, t0, t1); ull w0l = pack2(t0), w0h = pack2(t1);
            unpk(wv1.x, t0, t1); ull w2l = pack2(t0), w2h = pack2(t1);
            unpk(wv0.y, t0, t1); ull w1l = pack2(t0), w1h = pack2(t1);
            unpk(wv1.y, t0, t1); ull w3l = pack2(t0), w3h = pack2(t1);
            unpk(uv0.x, t0, t1); ull u0l = pack2(t0), u0h = pack2(t1);
            unpk(uv1.x, t0, t1); ull u2l = pack2(t0), u2h = pack2(t1);
            unpk(uv0.y, t0, t1); ull u1l = pack2(t0), u1h = pack2(t1);
            unpk(uv1.y, t0, t1); ull u3l = pack2(t0), u3h = pack2(t1);
            #pragma unroll
            for (int q = 0; q < 2; q++) {
                ulonglong2 h1v = *(const ulonglong2*)&sh1[g][q][k];
                ulonglong2 h2v = *(const ulonglong2*)&sh2[g][q][k];
                mL[0][q] = ffma2(h1v.x, w0l, mL[0][q]);
                mH[0][q] = ffma2(h1v.x, w0h, mH[0][q]);
                mL[1][q] = ffma2(h1v.x, w2l, mL[1][q]);
                mH[1][q] = ffma2(h1v.x, w2h, mH[1][q]);
                cL[0][q] = ffma2(h2v.x, u0l, cL[0][q]);
                cH[0][q] = ffma2(h2v.x, u0h, cH[0][q]);
                cL[1][q] = ffma2(h2v.x, u2l, cL[1][q]);
                cH[1][q] = ffma2(h2v.x, u2h, cH[1][q]);
                mL[0][q] = ffma2(h1v.y, w1l, mL[0][q]);
                mH[0][q] = ffma2(h1v.y, w1h, mH[0][q]);
                mL[1][q] = ffma2(h1v.y, w3l, mL[1][q]);
                mH[1][q] = ffma2(h1v.y, w3h, mH[1][q]);
                cL[0][q] = ffma2(h2v.y, u1l, cL[0][q]);
                cH[0][q] = ffma2(h2v.y, u1h, cH[0][q]);
                cL[1][q] = ffma2(h2v.y, u3l, cL[1][q]);
                cH[1][q] = ffma2(h2v.y, u3h, cH[1][q]);
            }
        }
        #pragma unroll
        for (int q = 0; q < 2; q++) {
            ss[g][q][lc]      = add2(mL[0][q], cL[0][q]);
            ss[g][q][lc + 16] = add2(mL[1][q], cL[1][q]);
            if (lc < 8) ss[g][q][lc + 32] = add2(mH[0][q], cH[0][q]);
            else { ss[g][q][lc + 32] = mH[0][q]; smh[g][q][lc - 8] = cH[0][q]; }
            ss[g][q][lc + 48] = mH[1][q];
            smh[g][q][lc + 8] = cH[1][q];
        }
        __syncwarp();
        {
            const ull* ssg  = &ss[g][0][0];
            const ull* smhg = &smh[g][0][0];
            ull* shg = &sh2[g][0][0];
            gate_unit(ssg, smhg, shg, 0, lc, hp2[0][0], hp2[0][1]);
            gate_unit(ssg, smhg, shg, q1r, i1r, hp2[1][0], hp2[1][1]);
            if (lc < 8) gate_unit(ssg, smhg, shg, 1, 12 + lc, hp2[2][0], hp2[2][1]);
        }
        __syncwarp();
    }

    // ---- dense head: logits = h2 @ Wd + bd (packed over batch pair) ----
    if (lc < NLABEL) {
        #pragma unroll
        for (int q = 0; q < 2; q++) {
            ull acc = pack2(bd[lc]);
            #pragma unroll
            for (int k = 0; k < HID; k++)
                acc = ffma2(sh2[g][q][k], pack2(Wd[k * NLABEL + lc]), acc);
            float o0, o1; unpk(acc, o0, o1);
            int e0 = b0 + 4 * g + 2 * q;
            out[(size_t)e0 * NLABEL + lc]       = o0;
            out[(size_t)(e0 + 1) * NLABEL + lc] = o1;
        }
    }
}

extern "C" void kernel_launch(void* const* d_in, const int* in_sizes, int n_in,
                              void* d_out, int out_size) {
    const int*   x   = (const int*)d_in[0];
    const float* emb = (const float*)d_in[1];
    const float* W1  = (const float*)d_in[2];
    const float* U1  = (const float*)d_in[3];
    const float* b1  = (const float*)d_in[4];
    const float* W2  = (const float*)d_in[5];
    const float* U2  = (const float*)d_in[6];
    const float* b2  = (const float*)d_in[7];
    const float* Wd  = (const float*)d_in[8];
    const float* bd  = (const float*)d_in[9];
    (void)in_sizes; (void)n_in; (void)out_size;

    proj1_kernel<<<512, 128>>>(emb, W1, b1);
    wordrnn_kernel<<<BATCHN / 8, 32>>>(
        x, U1, b1, W2, b2, U2, Wd, bd, (float*)d_out);
}

// round 16
// speedup vs baseline: 1.6084x; 1.6084x over previous
#include <cuda_runtime.h>

#define BATCHN 8192
#define SEQ 100
#define EMBED 50
#define HID 20
#define NLABEL 15
#define G3 60
#define VOCAB 50000

typedef unsigned long long ull;

// scratch: PW1[v] = emb[v] @ W1 + b1_input, pair-col-packed (col j, col j+32)
__device__ ull d_PW1p[(size_t)VOCAB * 32];

__device__ __forceinline__ ull pack2(float x) {
    ull d; asm("mov.b64 %0, {%1, %1};" : "=l"(d) : "f"(x)); return d;
}
__device__ __forceinline__ ull packab(float a, float b) {
    ull d; asm("mov.b64 %0, {%1, %2};" : "=l"(d) : "f"(a), "f"(b)); return d;
}
__device__ __forceinline__ void unpk(ull v, float &a, float &b) {
    asm("mov.b64 {%0, %1}, %2;" : "=f"(a), "=f"(b) : "l"(v));
}
__device__ __forceinline__ ull ffma2(ull a, ull b, ull c) {
    ull d; asm("fma.rn.f32x2 %0, %1, %2, %3;" : "=l"(d) : "l"(a), "l"(b), "l"(c)); return d;
}
__device__ __forceinline__ ull add2(ull a, ull b) {
    ull d; asm("add.rn.f32x2 %0, %1, %2;" : "=l"(d) : "l"(a), "l"(b)); return d;
}
// HW tanh (MUFU.TANH): 1 MUFU op. Measured rel_err 5.4e-6 on this model (R14).
__device__ __forceinline__ float tanhfast(float x) {
    float y; asm("tanh.approx.f32 %0, %1;" : "=f"(y) : "f"(x)); return y;
}
__device__ __forceinline__ float sigm(float x) {
    return fmaf(0.5f, tanhfast(0.5f * x), 0.5f);
}
__device__ __forceinline__ float tanh_(float x) {
    return tanhfast(x);
}

// ============================================================================
// proj: PW1[v] = emb[v]@W1 + bi1 (block-tiled, coalesced)
// ============================================================================
__global__ void __launch_bounds__(128) proj1_kernel(
    const float* __restrict__ emb, const float* __restrict__ W1,
    const float* __restrict__ b1)
{
    __shared__ __align__(16) ull sx[32 * EMBED];
    const int tid = threadIdx.x;
    const int w = tid >> 5, j = tid & 31;

    ull w1r[EMBED];
    #pragma unroll
    for (int k = 0; k < EMBED; k++) {
        float lo = W1[k * G3 + j];
        float hi = (j + 32 < G3) ? W1[k * G3 + j + 32] : 0.f;
        w1r[k] = packab(lo, hi);
    }
    const ull bias = packab(b1[j], (j + 32 < G3) ? b1[j + 32] : 0.f);

    const int ntiles = (VOCAB + 31) / 32;
    for (int tile = blockIdx.x; tile < ntiles; tile += gridDim.x) {
        const int row0 = tile * 32;
        const int nrow = (VOCAB - row0 < 32) ? (VOCAB - row0) : 32;
        for (int i = tid; i < nrow * EMBED; i += 128)
            sx[i] = pack2(emb[(size_t)row0 * EMBED + i]);
        __syncthreads();
        #pragma unroll
        for (int rr = 0; rr < 8; rr++) {
            int lr = w * 8 + rr;
            if (row0 + lr < VOCAB) {
                ull acc = bias;
                #pragma unroll
                for (int k = 0; k < EMBED; k += 2) {
                    ulonglong2 xv = *(const ulonglong2*)&sx[lr * EMBED + k];
                    acc = ffma2(xv.x, w1r[k], acc);
                    acc = ffma2(xv.y, w1r[k + 1], acc);
                }
                d_PW1p[(size_t)(row0 + lr) * 32 + j] = acc;
            }
        }
        __syncthreads();
    }
}

// ============================================================================
// Gate evaluation for one (q, i) unit: reads batch-paired sums, writes h
// batch-paired. tanh.approx-based gates (3 MUFU / unit).
// ============================================================================
__device__ __forceinline__ void gate_unit(
    const ull* __restrict__ ssg, const ull* __restrict__ smhg,
    ull* __restrict__ shg, int q, int i, float &hpa, float &hpb)
{
    float z0, z1, r0, r1, x0, x1, m0, m1;
    unpk(ssg[q * 64 + i],      z0, z1);
    unpk(ssg[q * 64 + i + 20], r0, r1);
    unpk(ssg[q * 64 + i + 40], x0, x1);
    unpk(smhg[q * 24 + i],     m0, m1);
    float za = sigm(z0), zb = sigm(z1);
    float ra = sigm(r0), rb = sigm(r1);
    float ha = tanh_(fmaf(ra, m0, x0));
    float hb = tanh_(fmaf(rb, m1, x1));
    float n0 = fmaf(za, hpa - ha, ha);
    float n1 = fmaf(zb, hpb - hb, hb);
    hpa = n0; hpb = n1;
    shg[q * HID + i] = packab(n0, n1);
}

// ============================================================================
// Fused 2-layer GRU. E=8 elements/warp via 16 col-lanes x 2 batch-groups.
// One warp per block (32 threads), 1024 blocks, syncwarp-only.
// (R8 structure verbatim; only the gate math changed to tanh.approx.)
// ============================================================================
__global__ void __launch_bounds__(32) wordrnn_kernel(
    const int* __restrict__ xg,
    const float* __restrict__ U1f, const float* __restrict__ b1,
    const float* __restrict__ W2f, const float* __restrict__ b2,
    const float* __restrict__ U2f,
    const float* __restrict__ Wd, const float* __restrict__ bd,
    float* __restrict__ out)
{
    __shared__ ull sU1[HID][32];          // (M[k][p], M[k][p+32]) per pair p
    __shared__ ull sW2[HID][32];
    __shared__ ull sU2[HID][32];
    __shared__ __align__(16) ull sh1[2][2][HID];   // [group][pair][k] = (h_e0, h_e1)
    __shared__ __align__(16) ull sh2[2][2][HID];
    __shared__ ull ss[2][2][64];          // packed gate sums per group/pair
    __shared__ ull smh[2][2][24];         // h-gate recurrent part
    __shared__ int sxi[8][SEQ];

    const int l = threadIdx.x;
    const int g = l >> 4, lc = l & 15;
    const int b0 = blockIdx.x * 8;

    // stage weights (pair-packed)
    for (int i = l; i < HID * 32; i += 32) {
        int k = i >> 5, c = i & 31;
        bool ok = (c + 32 < G3);
        int ch = ok ? c + 32 : 0;
        sU1[k][c] = packab(U1f[k * G3 + c], ok ? U1f[k * G3 + ch] : 0.f);
        sW2[k][c] = packab(W2f[k * G3 + c], ok ? W2f[k * G3 + ch] : 0.f);
        sU2[k][c] = packab(U2f[k * G3 + c], ok ? U2f[k * G3 + ch] : 0.f);
    }
    // stage indices: 8 rows x 100
    for (int i = l; i < 8 * 25; i += 32) {
        int r = i / 25, c = i % 25;
        *(int4*)&sxi[r][c * 4] = *(const int4*)(xg + (size_t)(b0 + r) * SEQ + c * 4);
    }
    for (int i = l; i < 2 * 2 * HID; i += 32) {
        ((ull*)sh1)[i] = 0ull;
        ((ull*)sh2)[i] = 0ull;
    }
    __syncwarp();

    // biases for this lane's col pairs p0=lc, p1=lc+16
    const int p0 = lc, p1 = lc + 16;
    const bool h1ok = (lc + 48 < G3);     // validity of col p1+32
    const ull br1L0 = pack2(b1[G3 + p0]), br1H0 = pack2(b1[G3 + p0 + 32]);
    const ull br1L1 = pack2(b1[G3 + p1]), br1H1 = pack2(h1ok ? b1[G3 + p1 + 32] : 0.f);
    const ull bi2L0 = pack2(b2[p0]),      bi2H0 = pack2(b2[p0 + 32]);
    const ull bi2L1 = pack2(b2[p1]),      bi2H1 = pack2(h1ok ? b2[p1 + 32] : 0.f);
    const ull br2L0 = pack2(b2[G3 + p0]), br2H0 = pack2(b2[G3 + p0 + 32]);
    const ull br2L1 = pack2(b2[G3 + p1]), br2H1 = pack2(h1ok ? b2[G3 + p1 + 32] : 0.f);

    // hprev for the 3 gate rounds (round -> fixed (q,i) per lane), 2 elems each
    float hp1[3][2] = {{0.f,0.f},{0.f,0.f},{0.f,0.f}};
    float hp2[3][2] = {{0.f,0.f},{0.f,0.f},{0.f,0.f}};
    const int q1r = (lc >= 4) ? 1 : 0;
    const int i1r = (lc < 4) ? 16 + lc : lc - 4;

    const ull* __restrict__ pw0 = d_PW1p + p0;
    const ull* __restrict__ pw1 = d_PW1p + p1;

    // t=0 input projection gather + 2x2 transpose into batch-pair packing
    ull axL[2][2], axH[2][2];
    #pragma unroll
    for (int q = 0; q < 2; q++) {
        int e0 = 4 * g + 2 * q;
        size_t i0 = (size_t)sxi[e0][0] * 32, i1 = (size_t)sxi[e0 + 1][0] * 32;
        ull ga = __ldg(pw0 + i0), gb = __ldg(pw0 + i1);
        ull gc = __ldg(pw1 + i0), gd = __ldg(pw1 + i1);
        float a0, a1, bb0, bb1, c0, c1, d0, d1;
        unpk(ga, a0, a1); unpk(gb, bb0, bb1);
        unpk(gc, c0, c1); unpk(gd, d0, d1);
        axL[0][q] = packab(a0, bb0); axH[0][q] = packab(a1, bb1);
        axL[1][q] = packab(c0, d0);  axH[1][q] = packab(c1, d1);
    }

    for (int t = 0; t < SEQ; t++) {
        // ================= layer 1: ah = h1 @ U1 + br1 =================
        ull aL[2][2], aH[2][2];
        aL[0][0] = br1L0; aL[0][1] = br1L0; aH[0][0] = br1H0; aH[0][1] = br1H0;
        aL[1][0] = br1L1; aL[1][1] = br1L1; aH[1][0] = br1H1; aH[1][1] = br1H1;
        #pragma unroll
        for (int kp = 0; kp < HID / 2; kp++) {
            const int k = kp * 2;
            ull wA0 = sU1[k][lc],     wA1 = sU1[k][lc + 16];
            ull wB0 = sU1[k + 1][lc], wB1 = sU1[k + 1][lc + 16];
            float t0, t1;
            unpk(wA0, t0, t1); ull wA0l = pack2(t0), wA0h = pack2(t1);
            unpk(wA1, t0, t1); ull wA1l = pack2(t0), wA1h = pack2(t1);
            unpk(wB0, t0, t1); ull wB0l = pack2(t0), wB0h = pack2(t1);
            unpk(wB1, t0, t1); ull wB1l = pack2(t0), wB1h = pack2(t1);
            ulonglong2 hv0 = *(const ulonglong2*)&sh1[g][0][k];
            ulonglong2 hv1 = *(const ulonglong2*)&sh1[g][1][k];
            aL[0][0] = ffma2(hv0.x, wA0l, aL[0][0]); aH[0][0] = ffma2(hv0.x, wA0h, aH[0][0]);
            aL[1][0] = ffma2(hv0.x, wA1l, aL[1][0]); aH[1][0] = ffma2(hv0.x, wA1h, aH[1][0]);
            aL[0][0] = ffma2(hv0.y, wB0l, aL[0][0]); aH[0][0] = ffma2(hv0.y, wB0h, aH[0][0]);
            aL[1][0] = ffma2(hv0.y, wB1l, aL[1][0]); aH[1][0] = ffma2(hv0.y, wB1h, aH[1][0]);
            aL[0][1] = ffma2(hv1.x, wA0l, aL[0][1]); aH[0][1] = ffma2(hv1.x, wA0h, aH[0][1]);
            aL[1][1] = ffma2(hv1.x, wA1l, aL[1][1]); aH[1][1] = ffma2(hv1.x, wA1h, aH[1][1]);
            aL[0][1] = ffma2(hv1.y, wB0l, aL[0][1]); aH[0][1] = ffma2(hv1.y, wB0h, aH[0][1]);
            aL[1][1] = ffma2(hv1.y, wB1l, aL[1][1]); aH[1][1] = ffma2(hv1.y, wB1h, aH[1][1]);
        }
        #pragma unroll
        for (int q = 0; q < 2; q++) {
            ss[g][q][lc]      = add2(axL[0][q], aL[0][q]);
            ss[g][q][lc + 16] = add2(axL[1][q], aL[1][q]);
            if (lc < 8) ss[g][q][lc + 32] = add2(axH[0][q], aH[0][q]);
            else { ss[g][q][lc + 32] = axH[0][q]; smh[g][q][lc - 8] = aH[0][q]; }
            ss[g][q][lc + 48] = axH[1][q];
            smh[g][q][lc + 8] = aH[1][q];
        }
        __syncwarp();
        {
            const ull* ssg  = &ss[g][0][0];
            const ull* smhg = &smh[g][0][0];
            ull* shg = &sh1[g][0][0];
            gate_unit(ssg, smhg, shg, 0, lc, hp1[0][0], hp1[0][1]);
            gate_unit(ssg, smhg, shg, q1r, i1r, hp1[1][0], hp1[1][1]);
            if (lc < 8) gate_unit(ssg, smhg, shg, 1, 12 + lc, hp1[2][0], hp1[2][1]);
        }
        __syncwarp();

        // prefetch next step's input projection (covered by layer-2 work)
        if (t + 1 < SEQ) {
            #pragma unroll
            for (int q = 0; q < 2; q++) {
                int e0 = 4 * g + 2 * q;
                size_t i0 = (size_t)sxi[e0][t + 1] * 32, i1 = (size_t)sxi[e0 + 1][t + 1] * 32;
                ull ga = __ldg(pw0 + i0), gb = __ldg(pw0 + i1);
                ull gc = __ldg(pw1 + i0), gd = __ldg(pw1 + i1);
                float a0, a1, bb0, bb1, c0, c1, d0, d1;
                unpk(ga, a0, a1); unpk(gb, bb0, bb1);
                unpk(gc, c0, c1); unpk(gd, d0, d1);
                axL[0][q] = packab(a0, bb0); axH[0][q] = packab(a1, bb1);
                axL[1][q] = packab(c0, d0);  axH[1][q] = packab(c1, d1);
            }
        }

        // ========== layer 2, pass A: m = h1 @ W2 + bi2 ==========
        ull mL[2][2], mH[2][2];
        mL[0][0] = bi2L0; mL[0][1] = bi2L0; mH[0][0] = bi2H0; mH[0][1] = bi2H0;
        mL[1][0] = bi2L1; mL[1][1] = bi2L1; mH[1][0] = bi2H1; mH[1][1] = bi2H1;
        #pragma unroll
        for (int kp = 0; kp < HID / 2; kp++) {
            const int k = kp * 2;
            ull wA0 = sW2[k][lc],     wA1 = sW2[k][lc + 16];
            ull wB0 = sW2[k + 1][lc], wB1 = sW2[k + 1][lc + 16];
            float t0, t1;
            unpk(wA0, t0, t1); ull wA0l = pack2(t0), wA0h = pack2(t1);
            unpk(wA1, t0, t1); ull wA1l = pack2(t0), wA1h = pack2(t1);
            unpk(wB0, t0, t1); ull wB0l = pack2(t0), wB0h = pack2(t1);
            unpk(wB1, t0, t1); ull wB1l = pack2(t0), wB1h = pack2(t1);
            ulonglong2 hv0 = *(const ulonglong2*)&sh1[g][0][k];
            ulonglong2 hv1 = *(const ulonglong2*)&sh1[g][1][k];
            mL[0][0] = ffma2(hv0.x, wA0l, mL[0][0]); mH[0][0] = ffma2(hv0.x, wA0h, mH[0][0]);
            mL[1][0] = ffma2(hv0.x, wA1l, mL[1][0]); mH[1][0] = ffma2(hv0.x, wA1h, mH[1][0]);
            mL[0][0] = ffma2(hv0.y, wB0l, mL[0][0]); mH[0][0] = ffma2(hv0.y, wB0h, mH[0][0]);
            mL[1][0] = ffma2(hv0.y, wB1l, mL[1][0]); mH[1][0] = ffma2(hv0.y, wB1h, mH[1][0]);
            mL[0][1] = ffma2(hv1.x, wA0l, mL[0][1]); mH[0][1] = ffma2(hv1.x, wA0h, mH[0][1]);
            mL[1][1] = ffma2(hv1.x, wA1l, mL[1][1]); mH[1][1] = ffma2(hv1.x, wA1h, mH[1][1]);
            mL[0][1] = ffma2(hv1.y, wB0l, mL[0][1]); mH[0][1] = ffma2(hv1.y, wB0h, mH[0][1]);
            mL[1][1] = ffma2(hv1.y, wB1l, mL[1][1]); mH[1][1] = ffma2(hv1.y, wB1h, mH[1][1]);
        }
        // ========== layer 2, pass B: c = h2 @ U2 + br2 ==========
        ull cL[2][2], cH[2][2];
        cL[0][0] = br2L0; cL[0][1] = br2L0; cH[0][0] = br2H0; cH[0][1] = br2H0;
        cL[1][0] = br2L1; cL[1][1] = br2L1; cH[1][0] = br2H1; cH[1][1] = br2H1;
        #pragma unroll
        for (int kp = 0; kp < HID / 2; kp++) {
            const int k = kp * 2;
            ull wA0 = sU2[k][lc],     wA1 = sU2[k][lc + 16];
            ull wB0 = sU2[k + 1][lc], wB1 = sU2[k + 1][lc + 16];
            float t0, t1;
            unpk(wA0, t0, t1); ull wA0l = pack2(t0), wA0h = pack2(t1);
            unpk(wA1, t0, t1); ull wA1l = pack2(t0), wA1h = pack2(t1);
            unpk(wB0, t0, t1); ull wB0l = pack2(t0), wB0h = pack2(t1);
            unpk(wB1, t0, t1); ull wB1l = pack2(t0), wB1h = pack2(t1);
            ulonglong2 hv0 = *(const ulonglong2*)&sh2[g][0][k];
            ulonglong2 hv1 = *(const ulonglong2*)&sh2[g][1][k];
            cL[0][0] = ffma2(hv0.x, wA0l, cL[0][0]); cH[0][0] = ffma2(hv0.x, wA0h, cH[0][0]);
            cL[1][0] = ffma2(hv0.x, wA1l, cL[1][0]); cH[1][0] = ffma2(hv0.x, wA1h, cH[1][0]);
            cL[0][0] = ffma2(hv0.y, wB0l, cL[0][0]); cH[0][0] = ffma2(hv0.y, wB0h, cH[0][0]);
            cL[1][0] = ffma2(hv0.y, wB1l, cL[1][0]); cH[1][0] = ffma2(hv0.y, wB1h, cH[1][0]);
            cL[0][1] = ffma2(hv1.x, wA0l, cL[0][1]); cH[0][1] = ffma2(hv1.x, wA0h, cH[0][1]);
            cL[1][1] = ffma2(hv1.x, wA1l, cL[1][1]); cH[1][1] = ffma2(hv1.x, wA1h, cH[1][1]);
            cL[0][1] = ffma2(hv1.y, wB0l, cL[0][1]); cH[0][1] = ffma2(hv1.y, wB0h, cH[0][1]);
            cL[1][1] = ffma2(hv1.y, wB1l, cL[1][1]); cH[1][1] = ffma2(hv1.y, wB1h, cH[1][1]);
        }
        #pragma unroll
        for (int q = 0; q < 2; q++) {
            ss[g][q][lc]      = add2(mL[0][q], cL[0][q]);
            ss[g][q][lc + 16] = add2(mL[1][q], cL[1][q]);
            if (lc < 8) ss[g][q][lc + 32] = add2(mH[0][q], cH[0][q]);
            else { ss[g][q][lc + 32] = mH[0][q]; smh[g][q][lc - 8] = cH[0][q]; }
            ss[g][q][lc + 48] = mH[1][q];
            smh[g][q][lc + 8] = cH[1][q];
        }
        __syncwarp();
        {
            const ull* ssg  = &ss[g][0][0];
            const ull* smhg = &smh[g][0][0];
            ull* shg = &sh2[g][0][0];
            gate_unit(ssg, smhg, shg, 0, lc, hp2[0][0], hp2[0][1]);
            gate_unit(ssg, smhg, shg, q1r, i1r, hp2[1][0], hp2[1][1]);
            if (lc < 8) gate_unit(ssg, smhg, shg, 1, 12 + lc, hp2[2][0], hp2[2][1]);
        }
        __syncwarp();
    }

    // ---- dense head: logits = h2 @ Wd + bd ----
    if (lc < NLABEL) {
        #pragma unroll
        for (int q = 0; q < 2; q++) {
            ull acc = pack2(bd[lc]);
            #pragma unroll
            for (int k = 0; k < HID; k++)
                acc = ffma2(sh2[g][q][k], pack2(Wd[k * NLABEL + lc]), acc);
            float o0, o1; unpk(acc, o0, o1);
            int e0 = b0 + 4 * g + 2 * q;
            out[(size_t)e0 * NLABEL + lc]       = o0;
            out[(size_t)(e0 + 1) * NLABEL + lc] = o1;
        }
    }
}

extern "C" void kernel_launch(void* const* d_in, const int* in_sizes, int n_in,
                              void* d_out, int out_size) {
    const int*   x   = (const int*)d_in[0];
    const float* emb = (const float*)d_in[1];
    const float* W1  = (const float*)d_in[2];
    const float* U1  = (const float*)d_in[3];
    const float* b1  = (const float*)d_in[4];
    const float* W2  = (const float*)d_in[5];
    const float* U2  = (const float*)d_in[6];
    const float* b2  = (const float*)d_in[7];
    const float* Wd  = (const float*)d_in[8];
    const float* bd  = (const float*)d_in[9];
    (void)in_sizes; (void)n_in; (void)out_size;

    proj1_kernel<<<512, 128>>>(emb, W1, b1);
    wordrnn_kernel<<<BATCHN / 8, 32>>>(
        x, U1, b1, W2, b2, U2, Wd, bd, (float*)d_out);
}